// round 6
// baseline (speedup 1.0000x reference)
#include <cuda_runtime.h>

// Problem constants (fixed shapes per setup_inputs)
#define N_PTS   65536
#define DLAT    64
#define KC      64
#define DDATA   512
#define ALPHA_F 0.001f
#define EPS_F   1e-8f
#define N_TILES (N_PTS / 64)
#define RS      68          // enc_s row stride (floats): 4*RS mod 32 = 16 -> no bank clash

// Scratch (device globals; no allocation allowed)
__device__ float g_C[KC * DLAT];
__device__ float g_Cnum[KC * DLAT];
__device__ float g_Cden[KC];
__device__ float g_loss;
__device__ float g_dec;

// ---------------------------------------------------------------------------
// Zero all accumulators (C itself is initialized by async D2D copy of enc[:64])
// ---------------------------------------------------------------------------
__global__ void init_kernel() {
    int i = blockIdx.x * blockDim.x + threadIdx.x;
    if (i < KC * DLAT) g_Cnum[i] = 0.f;
    if (i < KC)        g_Cden[i] = 0.f;
    if (i == 0) { g_loss = 0.f; g_dec = 0.f; }
}

// ---------------------------------------------------------------------------
// Decoder loss: sum((X - Dc)^2), float4 grid-stride, block-reduced atomicAdd
// ---------------------------------------------------------------------------
__global__ __launch_bounds__(256) void dec_kernel(const float4* __restrict__ X,
                                                  const float4* __restrict__ Dc,
                                                  int n4) {
    float acc = 0.f;
    int stride = gridDim.x * blockDim.x;
    for (int i = blockIdx.x * blockDim.x + threadIdx.x; i < n4; i += stride) {
        float4 a = X[i], b = Dc[i];
        float d0 = a.x - b.x, d1 = a.y - b.y, d2 = a.z - b.z, d3 = a.w - b.w;
        acc += d0 * d0 + d1 * d1 + d2 * d2 + d3 * d3;
    }
    __shared__ float red[8];
    #pragma unroll
    for (int o = 16; o; o >>= 1) acc += __shfl_xor_sync(0xffffffffu, acc, o);
    int w = threadIdx.x >> 5;
    if ((threadIdx.x & 31) == 0) red[w] = acc;
    __syncthreads();
    if (threadIdx.x < 32) {
        float v = (threadIdx.x < 8) ? red[threadIdx.x] : 0.f;
        #pragma unroll
        for (int o = 4; o; o >>= 1) v += __shfl_xor_sync(0xffffffffu, v, o);
        if (threadIdx.x == 0) atomicAdd(&g_dec, v);
    }
}

// ---------------------------------------------------------------------------
// Fused k-means iteration:
//   d2 = |x|^2 + |c|^2 - 2 x.c  (clamped >= 0), r = softmax(-d2),
//   Cnum += r^T enc, Cden += sum_p r   (skipped on last iter)
//   loss += sum_p sum_k r*d2           (only on last iter)
// Thread layout: 256 threads = (tx 0..15 -> 4 k's) x (ty 0..15 -> 4 p's / 4 d's)
// ---------------------------------------------------------------------------
__global__ __launch_bounds__(256) void assign_kernel(const float* __restrict__ enc,
                                                     int last) {
    extern __shared__ float smem[];
    float* enc_s = smem;               // 64 x RS   : enc tile [p][d]
    float* ct_s  = enc_s + 64 * RS;    // 64 x 64   : C transposed [d][k]
    float* r_s   = ct_s + 4096;        // 64 x 64   : r [p][k]
    float* x2_s  = r_s + 4096;         // 64
    float* c2_s  = x2_s + 64;          // 64
    float* red_s = c2_s + 64;          // 8

    int tid = threadIdx.x;
    int tx = tid & 15, ty = tid >> 4;
    int pb = ty * 4;                   // p-base (phase A) == d-base (phase B)
    int kb = tx * 4;                   // k-base

    // Stage C transposed (conflict-free shared stores: consecutive k per i)
    for (int i = tid; i < KC * DLAT; i += 256) {
        int k = i & 63, d = i >> 6;
        ct_s[d * 64 + k] = g_C[k * 64 + d];
    }
    __syncthreads();
    if (tid < KC) {
        float s = 0.f;
        #pragma unroll 8
        for (int d = 0; d < DLAT; d++) { float v = ct_s[d * 64 + tid]; s += v * v; }
        c2_s[tid] = s;
    }
    __syncthreads();

    float cn[4][4] = {};
    float den[4] = {};
    float lacc = 0.f;

    for (int tile = blockIdx.x; tile < N_TILES; tile += gridDim.x) {
        // ---- load enc tile (coalesced float4) ----
        const float4* eg = (const float4*)(enc + (size_t)tile * 4096);
        #pragma unroll
        for (int i = 0; i < 4; i++) {
            int lin = tid + i * 256;           // 1024 float4s
            int row = lin >> 4, c4 = lin & 15;
            *(float4*)&enc_s[row * RS + c4 * 4] = eg[lin];
        }
        __syncthreads();
        if (tid < 64) {
            float s = 0.f;
            const float* xr = &enc_s[tid * RS];
            #pragma unroll 8
            for (int d = 0; d < DLAT; d++) s += xr[d] * xr[d];
            x2_s[tid] = s;
        }
        __syncthreads();

        // ---- phase A: 4p x 4k dot products over D=64 ----
        float acc[4][4] = {};
        #pragma unroll 4
        for (int d4 = 0; d4 < DLAT; d4 += 4) {
            float4 xv0 = *(const float4*)&enc_s[(pb + 0) * RS + d4];
            float4 xv1 = *(const float4*)&enc_s[(pb + 1) * RS + d4];
            float4 xv2 = *(const float4*)&enc_s[(pb + 2) * RS + d4];
            float4 xv3 = *(const float4*)&enc_s[(pb + 3) * RS + d4];
            #pragma unroll
            for (int dd = 0; dd < 4; dd++) {
                float4 cv = *(const float4*)&ct_s[(d4 + dd) * 64 + kb];
                float a0 = ((const float*)&xv0)[dd];
                float a1 = ((const float*)&xv1)[dd];
                float a2 = ((const float*)&xv2)[dd];
                float a3 = ((const float*)&xv3)[dd];
                acc[0][0] += a0 * cv.x; acc[0][1] += a0 * cv.y; acc[0][2] += a0 * cv.z; acc[0][3] += a0 * cv.w;
                acc[1][0] += a1 * cv.x; acc[1][1] += a1 * cv.y; acc[1][2] += a1 * cv.z; acc[1][3] += a1 * cv.w;
                acc[2][0] += a2 * cv.x; acc[2][1] += a2 * cv.y; acc[2][2] += a2 * cv.z; acc[2][3] += a2 * cv.w;
                acc[3][0] += a3 * cv.x; acc[3][1] += a3 * cv.y; acc[3][2] += a3 * cv.z; acc[3][3] += a3 * cv.w;
            }
        }

        // ---- softmax over k (16 tx-lanes x 4 regs); loss on last iter ----
        #pragma unroll
        for (int pp = 0; pp < 4; pp++) {
            float x2p = x2_s[pb + pp];
            float d2v[4];
            float mn = 3.402823e38f;
            #pragma unroll
            for (int kk = 0; kk < 4; kk++) {
                float v = fmaxf(fmaf(-2.f, acc[pp][kk], x2p + c2_s[kb + kk]), 0.f);
                d2v[kk] = v;
                mn = fminf(mn, v);
            }
            #pragma unroll
            for (int o = 8; o; o >>= 1) mn = fminf(mn, __shfl_xor_sync(0xffffffffu, mn, o));
            float e0 = __expf(mn - d2v[0]);
            float e1 = __expf(mn - d2v[1]);
            float e2 = __expf(mn - d2v[2]);
            float e3 = __expf(mn - d2v[3]);
            float s = e0 + e1 + e2 + e3;
            #pragma unroll
            for (int o = 8; o; o >>= 1) s += __shfl_xor_sync(0xffffffffu, s, o);
            float inv = 1.f / s;
            if (last) {
                float l = (e0 * d2v[0] + e1 * d2v[1] + e2 * d2v[2] + e3 * d2v[3]) * inv;
                #pragma unroll
                for (int o = 8; o; o >>= 1) l += __shfl_xor_sync(0xffffffffu, l, o);
                if (tx == 0) lacc += l;
            } else {
                *(float4*)&r_s[(pb + pp) * 64 + kb] =
                    make_float4(e0 * inv, e1 * inv, e2 * inv, e3 * inv);
            }
        }

        // ---- phase B: rank-64 update, 4k x 4d register accumulators ----
        if (!last) {
            __syncthreads();
            #pragma unroll 4
            for (int p = 0; p < 64; p++) {
                float4 rv = *(const float4*)&r_s[p * 64 + kb];
                float4 ev = *(const float4*)&enc_s[p * RS + pb];
                cn[0][0] += rv.x * ev.x; cn[0][1] += rv.x * ev.y; cn[0][2] += rv.x * ev.z; cn[0][3] += rv.x * ev.w;
                cn[1][0] += rv.y * ev.x; cn[1][1] += rv.y * ev.y; cn[1][2] += rv.y * ev.z; cn[1][3] += rv.y * ev.w;
                cn[2][0] += rv.z * ev.x; cn[2][1] += rv.z * ev.y; cn[2][2] += rv.z * ev.z; cn[2][3] += rv.z * ev.w;
                cn[3][0] += rv.w * ev.x; cn[3][1] += rv.w * ev.y; cn[3][2] += rv.w * ev.z; cn[3][3] += rv.w * ev.w;
                if (ty == 0) { den[0] += rv.x; den[1] += rv.y; den[2] += rv.z; den[3] += rv.w; }
            }
        }
        __syncthreads();  // before next tile overwrites enc_s / r_s
    }

    // ---- block epilogue ----
    if (!last) {
        #pragma unroll
        for (int kk = 0; kk < 4; kk++)
            #pragma unroll
            for (int dd = 0; dd < 4; dd++)
                atomicAdd(&g_Cnum[(kb + kk) * 64 + pb + dd], cn[kk][dd]);
        if (ty == 0) {
            #pragma unroll
            for (int kk = 0; kk < 4; kk++) atomicAdd(&g_Cden[kb + kk], den[kk]);
        }
    } else {
        #pragma unroll
        for (int o = 16; o; o >>= 1) lacc += __shfl_xor_sync(0xffffffffu, lacc, o);
        int w = tid >> 5;
        if ((tid & 31) == 0) red_s[w] = lacc;
        __syncthreads();
        if (tid < 32) {
            float v = (tid < 8) ? red_s[tid] : 0.f;
            #pragma unroll
            for (int o = 4; o; o >>= 1) v += __shfl_xor_sync(0xffffffffu, v, o);
            if (tid == 0) atomicAdd(&g_loss, v);
        }
    }
}

// ---------------------------------------------------------------------------
// C = Cnum / (Cden + eps); re-zero accumulators. One block, internally synced.
// ---------------------------------------------------------------------------
__global__ void finalize_kernel() {
    __shared__ float den_s[KC];
    int tid = threadIdx.x;
    if (tid < KC) den_s[tid] = g_Cden[tid] + EPS_F;
    __syncthreads();
    for (int i = tid; i < KC * DLAT; i += 1024) {
        g_C[i] = g_Cnum[i] / den_s[i >> 6];
        g_Cnum[i] = 0.f;
    }
    if (tid < KC) g_Cden[tid] = 0.f;
}

__global__ void combine_kernel(float* out) {
    out[0] = g_dec * (1.f / (float)(N_PTS * (long long)DDATA))
           + ALPHA_F * g_loss * (1.f / (float)N_PTS);
}

// ---------------------------------------------------------------------------
#define SMEM_BYTES ((64 * RS + 4096 + 4096 + 64 + 64 + 8) * (int)sizeof(float))

extern "C" void kernel_launch(void* const* d_in, const int* in_sizes, int n_in,
                              void* d_out, int out_size) {
    const float* X   = (const float*)d_in[0];
    const float* enc = (const float*)d_in[1];
    const float* dcd = (const float*)d_in[2];
    float* out = (float*)d_out;

    // >48KB dynamic smem opt-in (host attribute set; idempotent, capture-safe)
    cudaFuncSetAttribute(assign_kernel,
                         cudaFuncAttributeMaxDynamicSharedMemorySize, SMEM_BYTES);

    // C init = enc[:K] (first 64 rows are contiguous)
    cudaMemcpyToSymbolAsync(g_C, enc, KC * DLAT * sizeof(float), 0,
                            cudaMemcpyDeviceToDevice, 0);
    init_kernel<<<17, 256>>>();
    dec_kernel<<<1184, 256>>>((const float4*)X, (const float4*)dcd,
                              (N_PTS * DDATA) / 4);
    for (int it = 0; it < 10; it++) {
        assign_kernel<<<148, 256, SMEM_BYTES>>>(enc, (it == 9) ? 1 : 0);
        if (it < 9) finalize_kernel<<<1, 1024>>>();
    }
    combine_kernel<<<1, 1>>>(out);
}